// round 7
// baseline (speedup 1.0000x reference)
#include <cuda_runtime.h>
#include <cstddef>

// BS=8, H=16, NUM_JOB=64, OPS_PER_JOB=32, DK=64, L=2048.
// op_mapping == [1]*32+[0]*32 per job => 8192 independent 32-token causal
// attention windows, RoPE positions 0..31, scale 1/8.
//
// Warp = one window.
//  QK: lane = query row; q row (RoPE'd+scaled) in regs; K (RoPE'd) in smem,
//      broadcast reads. Softmax fully in-lane.
//  WV: lane (rg=lane>>2, cg=lane&3) owns out rows 4rg..4rg+3 and the strided
//      column set {16t+4cg..16t+4cg+3 : t=0..3}; V read directly from GMEM
//      (L1-resident, L2-prefetched); weights fetched via shfl from row-lanes.

#define WPB 2

__device__ float4 g_rope[32 * 16];   // [pos][m]: (cos,sin) for pairs 2m,2m+1

__device__ __forceinline__ unsigned long long pack2(float a, float b) {
    unsigned long long r;
    asm("mov.b64 %0, {%1, %2};" : "=l"(r) : "f"(a), "f"(b));
    return r;
}
__device__ __forceinline__ void fma2(unsigned long long &d, unsigned long long a,
                                     unsigned long long b) {
    asm("fma.rn.f32x2 %0, %1, %2, %0;" : "+l"(d) : "l"(a), "l"(b));
}
__device__ __forceinline__ void add2(unsigned long long &d, unsigned long long a) {
    asm("add.rn.f32x2 %0, %0, %1;" : "+l"(d) : "l"(a));
}
__device__ __forceinline__ float2 unpack2(unsigned long long v) {
    float2 r;
    asm("mov.b64 {%0, %1}, %2;" : "=f"(r.x), "=f"(r.y) : "l"(v));
    return r;
}

__global__ void rope_init_kernel() {
    int t = blockIdx.x * 32 + threadIdx.x;   // 0..511
    int pos = t >> 4;
    int m   = t & 15;
    const double ln1e4_over32 = 9.210340371976184 / 32.0;
    double th0 = exp(-(double)(2 * m)     * ln1e4_over32);
    double th1 = exp(-(double)(2 * m + 1) * ln1e4_over32);
    double s0, c0, s1, c1;
    sincos((double)pos * th0, &s0, &c0);
    sincos((double)pos * th1, &s1, &c1);
    g_rope[t] = make_float4((float)c0, (float)s0, (float)c1, (float)s1);
}

__global__ __launch_bounds__(32 * WPB, 8)
void win_attn_kernel(const float* __restrict__ q,
                     const float* __restrict__ k,
                     const float* __restrict__ v,
                     float* __restrict__ out) {
    // ONE 8KB region per warp: q staging, then K. V never touches smem.
    __shared__ __align__(16) float4 S[WPB][512];

    const int warp = threadIdx.x >> 5;
    const int lane = threadIdx.x & 31;
    const int job  = blockIdx.x * WPB + warp;   // 0..8191
    const int b  = job >> 10;
    const int h  = (job >> 6) & 15;
    const int jb = job & 63;

    const size_t base = ((size_t)(b * 16 + h) * 2048 + (size_t)jb * 32) * 64;
    const float4* qg = (const float4*)(q + base);
    const float4* kg = (const float4*)(k + base);
    const float4* vg = (const float4*)(v + base);
    float4* R = S[warp];

    // Warm L2 for V (used late; each lane prefetches 2 of the 64 lines).
    {
        const char* vp = (const char*)vg + (size_t)lane * 256;
        asm volatile("prefetch.global.L2 [%0];" :: "l"(vp));
        asm volatile("prefetch.global.L2 [%0];" :: "l"(vp + 128));
    }

    // ---- Phase A: stage q coalesced (RoPE + 0.125), swizzled slots ----
#pragma unroll
    for (int i = 0; i < 16; i++) {
        const int f = i * 32 + lane;
        const int row = f >> 4, c4 = f & 15;
        float4 t = g_rope[row * 16 + c4];
        float4 x = qg[f];
        float4 o;
        o.x = (x.x * t.x - x.y * t.y) * 0.125f;
        o.y = (x.y * t.x + x.x * t.y) * 0.125f;
        o.z = (x.z * t.z - x.w * t.w) * 0.125f;
        o.w = (x.w * t.z + x.z * t.w) * 0.125f;
        R[row * 16 + (c4 ^ (row & 15))] = o;
    }
    __syncwarp();

    // ---- Phase B: lane pulls its own q row into packed regs ----
    unsigned long long qp[32];
#pragma unroll
    for (int c4 = 0; c4 < 16; c4++) {
        float4 x = R[lane * 16 + (c4 ^ (lane & 15))];
        qp[2 * c4]     = pack2(x.x, x.y);
        qp[2 * c4 + 1] = pack2(x.z, x.w);
    }
    __syncwarp();

    // ---- Phase C: stage K coalesced (RoPE), same region/swizzle ----
#pragma unroll
    for (int i = 0; i < 16; i++) {
        const int f = i * 32 + lane;
        const int row = f >> 4, c4 = f & 15;
        float4 t = g_rope[row * 16 + c4];
        float4 x = kg[f];
        float4 o;
        o.x = x.x * t.x - x.y * t.y;
        o.y = x.y * t.x + x.x * t.y;
        o.z = x.z * t.z - x.w * t.w;
        o.w = x.w * t.z + x.z * t.w;
        R[row * 16 + (c4 ^ (row & 15))] = o;
    }
    __syncwarp();

    // ---- Phase D: scores s[p] = q_lane . k_p (broadcast LDS) ----
    float s[32];
    const ulonglong2* KK = (const ulonglong2*)R;
#pragma unroll
    for (int p = 0; p < 32; p++) {
        unsigned long long a0 = 0ull, a1 = 0ull;
#pragma unroll
        for (int c4 = 0; c4 < 16; c4++) {
            ulonglong2 kv = KK[p * 16 + (c4 ^ (p & 15))];
            fma2(a0, kv.x, qp[2 * c4]);
            fma2(a1, kv.y, qp[2 * c4 + 1]);
        }
        add2(a0, a1);
        float2 f = unpack2(a0);
        s[p] = f.x + f.y;
    }

    // ---- Phase E: causal softmax, fully in-lane (lane = row) ----
#pragma unroll
    for (int p = 1; p < 32; p++)
        if (p > lane) s[p] = -1e30f;
    float m = s[0];
#pragma unroll
    for (int p = 1; p < 32; p++) m = fmaxf(m, s[p]);
    float sum = 0.f;
#pragma unroll
    for (int p = 0; p < 32; p++) {
        float e = __expf(s[p] - m);
        s[p] = e;
        sum += e;
    }
    const float inv = 1.0f / sum;
#pragma unroll
    for (int p = 0; p < 32; p++) s[p] *= inv;   // s[] now holds weights

    // ---- Phase F: O = W * V, V straight from GMEM (L1-resident) ----
    const int rg = lane >> 2;    // out rows 4rg..4rg+3
    const int cg = lane & 3;     // strided cols: float4 index 4t + cg
    unsigned long long aA[4][4], aB[4][4];
#pragma unroll
    for (int r = 0; r < 4; r++)
#pragma unroll
        for (int t = 0; t < 4; t++) { aA[r][t] = 0ull; aB[r][t] = 0ull; }

#pragma unroll
    for (int p = 0; p < 32; p++) {
        float w0 = __shfl_sync(0xffffffffu, s[p], 4 * rg + 0);
        float w1 = __shfl_sync(0xffffffffu, s[p], 4 * rg + 1);
        float w2 = __shfl_sync(0xffffffffu, s[p], 4 * rg + 2);
        float w3 = __shfl_sync(0xffffffffu, s[p], 4 * rg + 3);
        unsigned long long wp0 = pack2(w0, w0);
        unsigned long long wp1 = pack2(w1, w1);
        unsigned long long wp2 = pack2(w2, w2);
        unsigned long long wp3 = pack2(w3, w3);
#pragma unroll
        for (int t = 0; t < 4; t++) {
            float4 vf = vg[p * 16 + 4 * t + cg];
            unsigned long long vx = pack2(vf.x, vf.y);
            unsigned long long vy = pack2(vf.z, vf.w);
            fma2(aA[0][t], vx, wp0); fma2(aB[0][t], vy, wp0);
            fma2(aA[1][t], vx, wp1); fma2(aB[1][t], vy, wp1);
            fma2(aA[2][t], vx, wp2); fma2(aB[2][t], vy, wp2);
            fma2(aA[3][t], vx, wp3); fma2(aB[3][t], vy, wp3);
        }
    }

    // ---- Phase G: stores. Per (r,t): 8 rows x 64B contiguous chunks ----
    float* ob = out + ((size_t)b * 2048 + (size_t)jb * 32) * 1024 + h * 64;
#pragma unroll
    for (int r = 0; r < 4; r++) {
        float* rowp = ob + (size_t)(4 * rg + r) * 1024;
#pragma unroll
        for (int t = 0; t < 4; t++) {
            ulonglong2* dst = (ulonglong2*)(rowp + 16 * t + 4 * cg);
            ulonglong2 st;
            st.x = aA[r][t];
            st.y = aB[r][t];
            *dst = st;
        }
    }
}

extern "C" void kernel_launch(void* const* d_in, const int* in_sizes, int n_in,
                              void* d_out, int out_size) {
    const float* q = (const float*)d_in[0];
    const float* k = (const float*)d_in[1];
    const float* v = (const float*)d_in[2];
    float* out = (float*)d_out;

    rope_init_kernel<<<16, 32>>>();
    const int blocks = (8 * 16 * 64) / WPB;   // 4096
    win_attn_kernel<<<blocks, 32 * WPB>>>(q, k, v, out);
}

// round 8
// speedup vs baseline: 1.4361x; 1.4361x over previous
#include <cuda_runtime.h>
#include <cstdint>
#include <cstddef>

// BS=8, H=16, NUM_JOB=64, OPS_PER_JOB=32, DK=64, L=2048.
// op_mapping == [1]*32+[0]*32 per job => 8192 independent 32-token causal
// attention windows, RoPE positions 0..31, scale 1/8.
//
// One warp per window. Both GEMMs on tensor cores:
//   S = Q K^T  via mma.m16n8k8 tf32, 3-pass split-tf32 (fp32-grade accuracy)
//   O = W V    same.
// Smem pitches chosen so every fragment-load pattern is bank-conflict-free:
//   Q/K pitch 68 (68%32==4), V pitch 72 (72%32==8), W pitch 36 (36%32==4).

#define QK_PITCH 68
#define V_PITCH  72
#define W_PITCH  36

__device__ float4 g_rope[32 * 16];   // [pos][m]: cos/sin for pairs 2m, 2m+1

__global__ void rope_init_kernel() {
    int tdx = blockIdx.x * 32 + threadIdx.x;   // 0..511
    int pos = tdx >> 4;
    int m   = tdx & 15;
    const double ln1e4_over32 = 9.210340371976184 / 32.0;
    double th0 = exp(-(double)(2 * m)     * ln1e4_over32);
    double th1 = exp(-(double)(2 * m + 1) * ln1e4_over32);
    double s0, c0, s1, c1;
    sincos((double)pos * th0, &s0, &c0);
    sincos((double)pos * th1, &s1, &c1);
    g_rope[tdx] = make_float4((float)c0, (float)s0, (float)c1, (float)s1);
}

__device__ __forceinline__ void split_tf32(float x, uint32_t &hi, uint32_t &lo) {
    float b;
    asm("cvt.rna.tf32.f32 %0, %1;" : "=f"(b) : "f"(x));
    hi = __float_as_uint(b);
    lo = __float_as_uint(x - b);   // exact residual; HW-truncation of it is eps^2
}

__device__ __forceinline__ void mma_tf32(float c[4], const uint32_t a[4],
                                         uint32_t b0, uint32_t b1) {
    asm("mma.sync.aligned.m16n8k8.row.col.f32.tf32.tf32.f32 "
        "{%0,%1,%2,%3}, {%4,%5,%6,%7}, {%8,%9}, {%0,%1,%2,%3};"
        : "+f"(c[0]), "+f"(c[1]), "+f"(c[2]), "+f"(c[3])
        : "r"(a[0]), "r"(a[1]), "r"(a[2]), "r"(a[3]), "r"(b0), "r"(b1));
}

__global__ __launch_bounds__(32, 8)
void win_attn_kernel(const float* __restrict__ q,
                     const float* __restrict__ k,
                     const float* __restrict__ v,
                     float* __restrict__ out) {
    __shared__ __align__(16) float sQ[32 * QK_PITCH];   // later reused for W
    __shared__ __align__(16) float sK[32 * QK_PITCH];
    __shared__ __align__(16) float sV[32 * V_PITCH];

    const int lane = threadIdx.x;
    const int job  = blockIdx.x;                 // 0..8191
    const int b  = job >> 10;
    const int h  = (job >> 6) & 15;
    const int jb = job & 63;

    const size_t base = ((size_t)(b * 16 + h) * 2048 + (size_t)jb * 32) * 64;
    const float4* qg = (const float4*)(q + base);
    const float4* kg = (const float4*)(k + base);
    const float4* vg = (const float4*)(v + base);

    // ---- stage Q (RoPE + 0.125), K (RoPE), V — all upfront, coalesced ----
#pragma unroll
    for (int i = 0; i < 16; i++) {
        const int f = i * 32 + lane;
        const int row = f >> 4, c4 = f & 15;
        float4 t = g_rope[row * 16 + c4];
        float4 x = qg[f];
        float4 o;
        o.x = (x.x * t.x - x.y * t.y) * 0.125f;
        o.y = (x.y * t.x + x.x * t.y) * 0.125f;
        o.z = (x.z * t.z - x.w * t.w) * 0.125f;
        o.w = (x.w * t.z + x.z * t.w) * 0.125f;
        *(float4*)&sQ[row * QK_PITCH + c4 * 4] = o;
        x = kg[f];
        float4 o2;
        o2.x = x.x * t.x - x.y * t.y;
        o2.y = x.y * t.x + x.x * t.y;
        o2.z = x.z * t.z - x.w * t.w;
        o2.w = x.w * t.z + x.z * t.w;
        *(float4*)&sK[row * QK_PITCH + c4 * 4] = o2;
        *(float4*)&sV[row * V_PITCH + c4 * 4] = vg[f];
    }
    __syncwarp();

    const int g = lane >> 2;    // fragment group (0..7)
    const int t = lane & 3;     // thread-in-group (0..3)

    // ================= QK^T : S[32][32], 2 m-tiles x 4 n-tiles ============
    float C[2][4][4];
#pragma unroll
    for (int m = 0; m < 2; m++)
#pragma unroll
        for (int nt = 0; nt < 4; nt++)
#pragma unroll
            for (int j = 0; j < 4; j++) C[m][nt][j] = 0.f;

#pragma unroll
    for (int kt = 0; kt < 8; kt++) {
        const int k0 = kt * 8;
        uint32_t Ab[2][4], As[2][4];
#pragma unroll
        for (int m = 0; m < 2; m++) {
            const float* r0 = &sQ[(m * 16 + g) * QK_PITCH + k0];
            const float* r1 = r0 + 8 * QK_PITCH;
            split_tf32(r0[t],     Ab[m][0], As[m][0]);
            split_tf32(r1[t],     Ab[m][1], As[m][1]);
            split_tf32(r0[t + 4], Ab[m][2], As[m][2]);
            split_tf32(r1[t + 4], Ab[m][3], As[m][3]);
        }
        uint32_t Bb[4][2], Bs[4][2];
#pragma unroll
        for (int nt = 0; nt < 4; nt++) {
            const float* rn = &sK[(nt * 8 + g) * QK_PITCH + k0];
            split_tf32(rn[t],     Bb[nt][0], Bs[nt][0]);
            split_tf32(rn[t + 4], Bb[nt][1], Bs[nt][1]);
        }
#pragma unroll
        for (int m = 0; m < 2; m++)
#pragma unroll
            for (int nt = 0; nt < 4; nt++) {
                mma_tf32(C[m][nt], Ab[m], Bb[nt][0], Bb[nt][1]);
                mma_tf32(C[m][nt], As[m], Bb[nt][0], Bb[nt][1]);
                mma_tf32(C[m][nt], Ab[m], Bs[nt][0], Bs[nt][1]);
            }
    }

    // ================= causal softmax on fragments, W -> smem =============
    // Fragment row map: c0/c1 -> row m*16+g, c2/c3 -> row m*16+g+8;
    // cols: 8*nt + 2t (+1). Row reductions across the 4 quad lanes.
    __syncwarp();                       // Q reads done; sQ becomes W
    float* sW = sQ;
#pragma unroll
    for (int m = 0; m < 2; m++) {
        const int rA = m * 16 + g;
        const int rB = rA + 8;
        float eA[8], eB[8];
        float mxA = -1e30f, mxB = -1e30f;
#pragma unroll
        for (int nt = 0; nt < 4; nt++) {
            const int c0 = 8 * nt + 2 * t;
            float a0 = (c0     <= rA) ? C[m][nt][0] : -1e30f;
            float a1 = (c0 + 1 <= rA) ? C[m][nt][1] : -1e30f;
            float b0 = (c0     <= rB) ? C[m][nt][2] : -1e30f;
            float b1 = (c0 + 1 <= rB) ? C[m][nt][3] : -1e30f;
            eA[2 * nt] = a0; eA[2 * nt + 1] = a1;
            eB[2 * nt] = b0; eB[2 * nt + 1] = b1;
            mxA = fmaxf(mxA, fmaxf(a0, a1));
            mxB = fmaxf(mxB, fmaxf(b0, b1));
        }
        mxA = fmaxf(mxA, __shfl_xor_sync(0xffffffffu, mxA, 1));
        mxA = fmaxf(mxA, __shfl_xor_sync(0xffffffffu, mxA, 2));
        mxB = fmaxf(mxB, __shfl_xor_sync(0xffffffffu, mxB, 1));
        mxB = fmaxf(mxB, __shfl_xor_sync(0xffffffffu, mxB, 2));
        float sA = 0.f, sB = 0.f;
#pragma unroll
        for (int j = 0; j < 8; j++) {
            eA[j] = __expf(eA[j] - mxA); sA += eA[j];
            eB[j] = __expf(eB[j] - mxB); sB += eB[j];
        }
        sA += __shfl_xor_sync(0xffffffffu, sA, 1);
        sA += __shfl_xor_sync(0xffffffffu, sA, 2);
        sB += __shfl_xor_sync(0xffffffffu, sB, 1);
        sB += __shfl_xor_sync(0xffffffffu, sB, 2);
        const float iA = 1.0f / sA;
        const float iB = 1.0f / sB;
#pragma unroll
        for (int nt = 0; nt < 4; nt++) {
            float2 wa = make_float2(eA[2 * nt] * iA, eA[2 * nt + 1] * iA);
            float2 wb = make_float2(eB[2 * nt] * iB, eB[2 * nt + 1] * iB);
            *(float2*)&sW[rA * W_PITCH + 8 * nt + 2 * t] = wa;
            *(float2*)&sW[rB * W_PITCH + 8 * nt + 2 * t] = wb;
        }
    }
    __syncwarp();

    // ================= O = W V : 2 m-tiles x 8 n-tiles, k=32 ==============
    // Keep all W A-fragments resident (big+small), loop n-tiles.
    uint32_t WAb[2][4][4], WAs[2][4][4];
#pragma unroll
    for (int kt = 0; kt < 4; kt++) {
        const int k0 = kt * 8;
#pragma unroll
        for (int m = 0; m < 2; m++) {
            const float* r0 = &sW[(m * 16 + g) * W_PITCH + k0];
            const float* r1 = r0 + 8 * W_PITCH;
            split_tf32(r0[t],     WAb[m][kt][0], WAs[m][kt][0]);
            split_tf32(r1[t],     WAb[m][kt][1], WAs[m][kt][1]);
            split_tf32(r0[t + 4], WAb[m][kt][2], WAs[m][kt][2]);
            split_tf32(r1[t + 4], WAb[m][kt][3], WAs[m][kt][3]);
        }
    }

    float* ob = out + ((size_t)b * 2048 + (size_t)jb * 32) * 1024 + h * 64;
#pragma unroll
    for (int nt = 0; nt < 8; nt++) {
        float Cw[2][4];
#pragma unroll
        for (int m = 0; m < 2; m++)
#pragma unroll
            for (int j = 0; j < 4; j++) Cw[m][j] = 0.f;

#pragma unroll
        for (int kt = 0; kt < 4; kt++) {
            const float* vp = &sV[(kt * 8 + t) * V_PITCH + nt * 8 + g];
            uint32_t b0b, b0s, b1b, b1s;
            split_tf32(vp[0],          b0b, b0s);   // V[kt*8+t  ][nt*8+g]
            split_tf32(vp[4 * V_PITCH], b1b, b1s);  // V[kt*8+t+4][nt*8+g]
#pragma unroll
            for (int m = 0; m < 2; m++) {
                mma_tf32(Cw[m], WAb[m][kt], b0b, b1b);
                mma_tf32(Cw[m], WAs[m][kt], b0b, b1b);
                mma_tf32(Cw[m], WAb[m][kt], b0s, b1s);
            }
        }
        // store: rows m*16+g (c0,c1) and +8 (c2,c3); cols 8*nt + 2t (+1)
#pragma unroll
        for (int m = 0; m < 2; m++) {
            const int rA = m * 16 + g;
            float* pA = ob + (size_t)rA * 1024 + 8 * nt + 2 * t;
            float* pB = pA + 8 * 1024;
            *(float2*)pA = make_float2(Cw[m][0], Cw[m][1]);
            *(float2*)pB = make_float2(Cw[m][2], Cw[m][3]);
        }
    }
}

extern "C" void kernel_launch(void* const* d_in, const int* in_sizes, int n_in,
                              void* d_out, int out_size) {
    const float* q = (const float*)d_in[0];
    const float* k = (const float*)d_in[1];
    const float* v = (const float*)d_in[2];
    float* out = (float*)d_out;

    // Maximize smem carveout so 8 blocks (8 warps) fit per SM.
    static bool configured = false;
    if (!configured) {
        cudaFuncSetAttribute(win_attn_kernel,
                             cudaFuncAttributePreferredSharedMemoryCarveout,
                             cudaSharedmemCarveoutMaxShared);
        configured = true;
    }

    rope_init_kernel<<<16, 32>>>();
    win_attn_kernel<<<8 * 16 * 64, 32>>>(q, k, v, out);
}

// round 11
// speedup vs baseline: 1.8709x; 1.3028x over previous
#include <cuda_runtime.h>
#include <cstdint>
#include <cstddef>

// BS=8, H=16, NUM_JOB=64, OPS_PER_JOB=32, DK=64, L=2048.
// op_mapping == [1]*32+[0]*32 per job => 8192 independent 32-token causal
// attention windows, RoPE positions 0..31, scale 1/8.
//
// One warp per window, ZERO shared memory.
// Permuted-k mma fragments: slot t -> data 2t, slot t+4 -> data 2t+1 (same
// permutation on A and B of both GEMMs => result unchanged). Consequences:
//  - Q/K fragments: direct float2 GMEM loads; RoPE pair lives in one thread.
//  - Softmaxed QK^T C-fragment IS the A-fragment of W for W*V (c0,c2,c1,c3).
//  - V fragments: direct GMEM loads.
// Both GEMMs: mma.m16n8k8 tf32, 3-pass split (fp32-grade accuracy).

__device__ float2 g_rope2[32 * 32];   // [row][j] = (cos, sin) for col pair 2j,2j+1

__global__ void rope_init_kernel() {
    int tdx = blockIdx.x * 32 + threadIdx.x;   // 0..1023
    int row = tdx >> 5;
    int j   = tdx & 31;                        // PAIR index (0..31)
    const double ln1e4_over32 = 9.210340371976184 / 32.0;
    // theta_j = 10000^(-j/32)  (pair index j; R9 bug was 10000^(-2j/32))
    double th = exp(-(double)j * ln1e4_over32);
    double s, c;
    sincos((double)row * th, &s, &c);
    g_rope2[tdx] = make_float2((float)c, (float)s);
}

__device__ __forceinline__ void split_tf32(float x, uint32_t &hi, uint32_t &lo) {
    float b;
    asm("cvt.rna.tf32.f32 %0, %1;" : "=f"(b) : "f"(x));
    hi = __float_as_uint(b);
    lo = __float_as_uint(x - b);
}

__device__ __forceinline__ void mma_tf32(float c[4], uint32_t a0, uint32_t a1,
                                         uint32_t a2, uint32_t a3,
                                         uint32_t b0, uint32_t b1) {
    asm("mma.sync.aligned.m16n8k8.row.col.f32.tf32.tf32.f32 "
        "{%0,%1,%2,%3}, {%4,%5,%6,%7}, {%8,%9}, {%0,%1,%2,%3};"
        : "+f"(c[0]), "+f"(c[1]), "+f"(c[2]), "+f"(c[3])
        : "r"(a0), "r"(a1), "r"(a2), "r"(a3), "r"(b0), "r"(b1));
}

__global__ __launch_bounds__(32, 16)
void win_attn_kernel(const float* __restrict__ q,
                     const float* __restrict__ k,
                     const float* __restrict__ v,
                     float* __restrict__ out) {
    const int lane = threadIdx.x;
    const int g = lane >> 2;    // fragment group 0..7
    const int t = lane & 3;     // thread-in-group 0..3
    const int job = blockIdx.x;                 // 0..8191
    const int b  = job >> 10;
    const int h  = (job >> 6) & 15;
    const int jb = job & 63;

    const size_t base = ((size_t)(b * 16 + h) * 2048 + (size_t)jb * 32) * 64;
    const float* Qb = q + base;
    const float* Kb = k + base;
    const float* Vb = v + base;

    // Warm L2 for V (consumed last); 32 lanes x 2 lines = 8KB tile.
    {
        const char* vp = (const char*)Vb + (size_t)lane * 256;
        asm volatile("prefetch.global.L2 [%0];" :: "l"(vp));
        asm volatile("prefetch.global.L2 [%0];" :: "l"(vp + 128));
    }

    // ================= QK^T : S[32][32], 2 m-tiles x 4 n-tiles =============
    float C[2][4][4];
#pragma unroll
    for (int m = 0; m < 2; m++)
#pragma unroll
        for (int nt = 0; nt < 4; nt++)
#pragma unroll
            for (int j = 0; j < 4; j++) C[m][nt][j] = 0.f;

#pragma unroll
    for (int kt = 0; kt < 8; kt++) {
        const int kc = kt * 8 + 2 * t;        // permuted k columns (2j, 2j+1)
        const int jj = kt * 4 + t;            // rope pair index

        // ---- Q A-fragments (RoPE + 0.125 scale in registers) ----
        uint32_t Ah[2][4], Al[2][4];
#pragma unroll
        for (int m = 0; m < 2; m++) {
            const int r0 = m * 16 + g;
            const int r1 = r0 + 8;
            float2 x0 = *(const float2*)(Qb + (size_t)r0 * 64 + kc);
            float2 x1 = *(const float2*)(Qb + (size_t)r1 * 64 + kc);
            float2 t0 = g_rope2[r0 * 32 + jj];
            float2 t1 = g_rope2[r1 * 32 + jj];
            float y0 = (x0.x * t0.x - x0.y * t0.y) * 0.125f;   // (r0, 2j)
            float y1 = (x0.y * t0.x + x0.x * t0.y) * 0.125f;   // (r0, 2j+1)
            float z0 = (x1.x * t1.x - x1.y * t1.y) * 0.125f;   // (r1, 2j)
            float z1 = (x1.y * t1.x + x1.x * t1.y) * 0.125f;   // (r1, 2j+1)
            split_tf32(y0, Ah[m][0], Al[m][0]);   // a0: (g,   slot t   ->2j)
            split_tf32(z0, Ah[m][1], Al[m][1]);   // a1: (g+8, 2j)
            split_tf32(y1, Ah[m][2], Al[m][2]);   // a2: (g,   slot t+4 ->2j+1)
            split_tf32(z1, Ah[m][3], Al[m][3]);   // a3: (g+8, 2j+1)
        }

        // ---- K B-fragments (RoPE in registers); n-col = g ----
        uint32_t Bh[4][2], Bl[4][2];
#pragma unroll
        for (int nt = 0; nt < 4; nt++) {
            const int r = nt * 8 + g;
            float2 x = *(const float2*)(Kb + (size_t)r * 64 + kc);
            float2 tt = g_rope2[r * 32 + jj];
            float y0 = x.x * tt.x - x.y * tt.y;   // (r, 2j)   -> b0
            float y1 = x.y * tt.x + x.x * tt.y;   // (r, 2j+1) -> b1
            split_tf32(y0, Bh[nt][0], Bl[nt][0]);
            split_tf32(y1, Bh[nt][1], Bl[nt][1]);
        }

#pragma unroll
        for (int m = 0; m < 2; m++)
#pragma unroll
            for (int nt = 0; nt < 4; nt++) {
                mma_tf32(C[m][nt], Ah[m][0], Ah[m][1], Ah[m][2], Ah[m][3],
                         Bh[nt][0], Bh[nt][1]);
                mma_tf32(C[m][nt], Al[m][0], Al[m][1], Al[m][2], Al[m][3],
                         Bh[nt][0], Bh[nt][1]);
                mma_tf32(C[m][nt], Ah[m][0], Ah[m][1], Ah[m][2], Ah[m][3],
                         Bl[nt][0], Bl[nt][1]);
            }
    }

    // ================= causal softmax on C fragments ========================
    // c0=(rA, 8nt+2t) c1=(rA, +1) c2=(rB, 2t) c3=(rB, +1); rA=m16+g, rB=rA+8.
#pragma unroll
    for (int m = 0; m < 2; m++) {
        const int rA = m * 16 + g;
        const int rB = rA + 8;
        float mxA = -1e30f, mxB = -1e30f;
#pragma unroll
        for (int nt = 0; nt < 4; nt++) {
            const int c0 = 8 * nt + 2 * t;
            if (c0     > rA) C[m][nt][0] = -1e30f;
            if (c0 + 1 > rA) C[m][nt][1] = -1e30f;
            if (c0     > rB) C[m][nt][2] = -1e30f;
            if (c0 + 1 > rB) C[m][nt][3] = -1e30f;
            mxA = fmaxf(mxA, fmaxf(C[m][nt][0], C[m][nt][1]));
            mxB = fmaxf(mxB, fmaxf(C[m][nt][2], C[m][nt][3]));
        }
        mxA = fmaxf(mxA, __shfl_xor_sync(0xffffffffu, mxA, 1));
        mxA = fmaxf(mxA, __shfl_xor_sync(0xffffffffu, mxA, 2));
        mxB = fmaxf(mxB, __shfl_xor_sync(0xffffffffu, mxB, 1));
        mxB = fmaxf(mxB, __shfl_xor_sync(0xffffffffu, mxB, 2));
        float sA = 0.f, sB = 0.f;
#pragma unroll
        for (int nt = 0; nt < 4; nt++) {
            C[m][nt][0] = __expf(C[m][nt][0] - mxA); sA += C[m][nt][0];
            C[m][nt][1] = __expf(C[m][nt][1] - mxA); sA += C[m][nt][1];
            C[m][nt][2] = __expf(C[m][nt][2] - mxB); sB += C[m][nt][2];
            C[m][nt][3] = __expf(C[m][nt][3] - mxB); sB += C[m][nt][3];
        }
        sA += __shfl_xor_sync(0xffffffffu, sA, 1);
        sA += __shfl_xor_sync(0xffffffffu, sA, 2);
        sB += __shfl_xor_sync(0xffffffffu, sB, 1);
        sB += __shfl_xor_sync(0xffffffffu, sB, 2);
        const float iA = 1.0f / sA;
        const float iB = 1.0f / sB;
#pragma unroll
        for (int nt = 0; nt < 4; nt++) {
            C[m][nt][0] *= iA;
            C[m][nt][1] *= iA;
            C[m][nt][2] *= iB;
            C[m][nt][3] *= iB;
        }
    }

    // ================= O = W V ; W A-frags == C frags (c0,c2,c1,c3) ========
    // kt-outer, nt in column halves; V direct from GMEM, each element once.
    float* ob = out + ((size_t)b * 2048 + (size_t)jb * 32) * 1024 + h * 64;
#pragma unroll
    for (int half = 0; half < 2; half++) {
        float Cw[2][4][4];
#pragma unroll
        for (int m = 0; m < 2; m++)
#pragma unroll
            for (int nti = 0; nti < 4; nti++)
#pragma unroll
                for (int j = 0; j < 4; j++) Cw[m][nti][j] = 0.f;

#pragma unroll
        for (int kt = 0; kt < 4; kt++) {
            // W fragments from softmaxed C (k-dim = key pos, tile kt):
            // a0=c0, a1=c2, a2=c1, a3=c3 — same permuted layout.
            uint32_t Wh[2][4], Wl[2][4];
#pragma unroll
            for (int m = 0; m < 2; m++) {
                split_tf32(C[m][kt][0], Wh[m][0], Wl[m][0]);
                split_tf32(C[m][kt][2], Wh[m][1], Wl[m][1]);
                split_tf32(C[m][kt][1], Wh[m][2], Wl[m][2]);
                split_tf32(C[m][kt][3], Wh[m][3], Wl[m][3]);
            }
            const int p0 = kt * 8 + 2 * t;     // permuted k rows of V
#pragma unroll
            for (int nti = 0; nti < 4; nti++) {
                const int ncol = (half * 4 + nti) * 8 + g;
                float v0 = Vb[(size_t)p0 * 64 + ncol];
                float v1 = Vb[(size_t)(p0 + 1) * 64 + ncol];
                uint32_t b0h, b0l, b1h, b1l;
                split_tf32(v0, b0h, b0l);
                split_tf32(v1, b1h, b1l);
#pragma unroll
                for (int m = 0; m < 2; m++) {
                    mma_tf32(Cw[m][nti], Wh[m][0], Wh[m][1], Wh[m][2], Wh[m][3],
                             b0h, b1h);
                    mma_tf32(Cw[m][nti], Wl[m][0], Wl[m][1], Wl[m][2], Wl[m][3],
                             b0h, b1h);
                    mma_tf32(Cw[m][nti], Wh[m][0], Wh[m][1], Wh[m][2], Wh[m][3],
                             b0l, b1l);
                }
            }
        }

        // stores: rows m16+g / +8, cols (half*4+nti)*8 + 2t (+1)
#pragma unroll
        for (int m = 0; m < 2; m++) {
            const int rA = m * 16 + g;
#pragma unroll
            for (int nti = 0; nti < 4; nti++) {
                float* pA = ob + (size_t)rA * 1024 + (half * 4 + nti) * 8 + 2 * t;
                float* pB = pA + 8 * 1024;
                *(float2*)pA = make_float2(Cw[m][nti][0], Cw[m][nti][1]);
                *(float2*)pB = make_float2(Cw[m][nti][2], Cw[m][nti][3]);
            }
        }
    }
}

extern "C" void kernel_launch(void* const* d_in, const int* in_sizes, int n_in,
                              void* d_out, int out_size) {
    const float* q = (const float*)d_in[0];
    const float* k = (const float*)d_in[1];
    const float* v = (const float*)d_in[2];
    float* out = (float*)d_out;

    rope_init_kernel<<<32, 32>>>();
    win_attn_kernel<<<8 * 16 * 64, 32>>>(q, k, v, out);
}

// round 12
// speedup vs baseline: 1.8864x; 1.0083x over previous
#include <cuda_runtime.h>
#include <cstdint>
#include <cstddef>

// BS=8, H=16, NUM_JOB=64, OPS_PER_JOB=32, DK=64, L=2048.
// op_mapping == [1]*32+[0]*32 per job => 8192 independent 32-token causal
// attention windows, RoPE positions 0..31, scale 1/8.
//
// One warp per window, ZERO shared memory. mma.m16n8k8 tf32, 3-pass split.
//
// Per-GEMM k-permutations (A and B of a GEMM share a permutation; the two
// GEMMs need not match):
//  QK: per 16-col double-tile ktp, thread t owns data cols {16ktp+4t..+3}
//      (tile0 slots t,t+4 -> cols 4t,4t+1; tile1 -> 4t+2,4t+3).
//      => Q/K fragment loads are float4; rope table reads are float4.
//  WV: slot t -> key 2t, slot t+4 -> key 2t+1 (matches QK's C layout, so the
//      softmaxed C fragment IS W's A fragment, order c0,c2,c1,c3).

__device__ float2 g_rope2[32 * 32];   // [row][j] = (cos, sin), pair j = cols 2j,2j+1

__global__ void rope_init_kernel() {
    int tdx = blockIdx.x * 32 + threadIdx.x;   // 0..1023
    int row = tdx >> 5;
    int j   = tdx & 31;                        // pair index
    const double ln1e4_over32 = 9.210340371976184 / 32.0;
    double th = exp(-(double)j * ln1e4_over32);   // theta_j = 10000^(-j/32)
    double s, c;
    sincos((double)row * th, &s, &c);
    g_rope2[tdx] = make_float2((float)c, (float)s);
}

__device__ __forceinline__ void split_tf32(float x, uint32_t &hi, uint32_t &lo) {
    float b;
    asm("cvt.rna.tf32.f32 %0, %1;" : "=f"(b) : "f"(x));
    hi = __float_as_uint(b);
    lo = __float_as_uint(x - b);
}

__device__ __forceinline__ void mma_tf32(float c[4], uint32_t a0, uint32_t a1,
                                         uint32_t a2, uint32_t a3,
                                         uint32_t b0, uint32_t b1) {
    asm("mma.sync.aligned.m16n8k8.row.col.f32.tf32.tf32.f32 "
        "{%0,%1,%2,%3}, {%4,%5,%6,%7}, {%8,%9}, {%0,%1,%2,%3};"
        : "+f"(c[0]), "+f"(c[1]), "+f"(c[2]), "+f"(c[3])
        : "r"(a0), "r"(a1), "r"(a2), "r"(a3), "r"(b0), "r"(b1));
}

__global__ __launch_bounds__(32, 18)
void win_attn_kernel(const float* __restrict__ q,
                     const float* __restrict__ k,
                     const float* __restrict__ v,
                     float* __restrict__ out) {
    const uint32_t lane = threadIdx.x;
    const uint32_t g = lane >> 2;    // fragment group 0..7
    const uint32_t t = lane & 3;     // thread-in-group 0..3
    const uint32_t job = blockIdx.x;            // 0..8191
    const uint32_t bh = job >> 6;               // b*16 + h
    const uint32_t jb = job & 63;

    const uint32_t base = bh * (2048u * 64u) + jb * (32u * 64u);
    const float* Qb = q + base;
    const float* Kb = k + base;
    const float* Vb = v + base;

    // Warm L2 for V (consumed last): 32 lanes x 2 lines = the 8KB tile.
    {
        const char* vp = (const char*)Vb + lane * 256u;
        asm volatile("prefetch.global.L2 [%0];" :: "l"(vp));
        asm volatile("prefetch.global.L2 [%0];" :: "l"(vp + 128));
    }

    const float4* rope4 = (const float4*)g_rope2;   // [row*16 + jj/2]

    // ================= QK^T : S[32][32], 2 m-tiles x 4 n-tiles =============
    float C[2][4][4];
#pragma unroll
    for (int m = 0; m < 2; m++)
#pragma unroll
        for (int nt = 0; nt < 4; nt++)
#pragma unroll
            for (int j = 0; j < 4; j++) C[m][nt][j] = 0.f;

#pragma unroll
    for (int ktp = 0; ktp < 4; ktp++) {
        const uint32_t c0 = ktp * 16u + 4u * t;   // this thread's 4 data cols
        const uint32_t ri = ktp * 4u + t;         // rope float4 slot in row

        // ---- rotated Q values (RoPE + 0.125), rows m16+g / +8 ----
        float yq[2][2][4];
#pragma unroll
        for (int m = 0; m < 2; m++) {
            const uint32_t r0 = m * 16u + g;
            const uint32_t r1 = r0 + 8u;
            float4 x0 = *(const float4*)(Qb + r0 * 64u + c0);
            float4 x1 = *(const float4*)(Qb + r1 * 64u + c0);
            float4 t0 = rope4[r0 * 16u + ri];
            float4 t1 = rope4[r1 * 16u + ri];
            yq[m][0][0] = (x0.x * t0.x - x0.y * t0.y) * 0.125f;
            yq[m][0][1] = (x0.y * t0.x + x0.x * t0.y) * 0.125f;
            yq[m][0][2] = (x0.z * t0.z - x0.w * t0.w) * 0.125f;
            yq[m][0][3] = (x0.w * t0.z + x0.z * t0.w) * 0.125f;
            yq[m][1][0] = (x1.x * t1.x - x1.y * t1.y) * 0.125f;
            yq[m][1][1] = (x1.y * t1.x + x1.x * t1.y) * 0.125f;
            yq[m][1][2] = (x1.z * t1.z - x1.w * t1.w) * 0.125f;
            yq[m][1][3] = (x1.w * t1.z + x1.z * t1.w) * 0.125f;
        }
        // ---- rotated K values, rows nt8+g ----
        float yk[4][4];
#pragma unroll
        for (int nt = 0; nt < 4; nt++) {
            const uint32_t r = nt * 8u + g;
            float4 x  = *(const float4*)(Kb + r * 64u + c0);
            float4 tt = rope4[r * 16u + ri];
            yk[nt][0] = x.x * tt.x - x.y * tt.y;
            yk[nt][1] = x.y * tt.x + x.x * tt.y;
            yk[nt][2] = x.z * tt.z - x.w * tt.w;
            yk[nt][3] = x.w * tt.z + x.z * tt.w;
        }

        // ---- two k8 tiles: sub=0 -> cols 4t,4t+1; sub=1 -> 4t+2,4t+3 ----
#pragma unroll
        for (int sub = 0; sub < 2; sub++) {
            uint32_t Ah[2][4], Al[2][4], Bh[4][2], Bl[4][2];
#pragma unroll
            for (int m = 0; m < 2; m++) {
                split_tf32(yq[m][0][2 * sub],     Ah[m][0], Al[m][0]);
                split_tf32(yq[m][1][2 * sub],     Ah[m][1], Al[m][1]);
                split_tf32(yq[m][0][2 * sub + 1], Ah[m][2], Al[m][2]);
                split_tf32(yq[m][1][2 * sub + 1], Ah[m][3], Al[m][3]);
            }
#pragma unroll
            for (int nt = 0; nt < 4; nt++) {
                split_tf32(yk[nt][2 * sub],     Bh[nt][0], Bl[nt][0]);
                split_tf32(yk[nt][2 * sub + 1], Bh[nt][1], Bl[nt][1]);
            }
#pragma unroll
            for (int m = 0; m < 2; m++)
#pragma unroll
                for (int nt = 0; nt < 4; nt++) {
                    mma_tf32(C[m][nt], Ah[m][0], Ah[m][1], Ah[m][2], Ah[m][3],
                             Bh[nt][0], Bh[nt][1]);
                    mma_tf32(C[m][nt], Al[m][0], Al[m][1], Al[m][2], Al[m][3],
                             Bh[nt][0], Bh[nt][1]);
                    mma_tf32(C[m][nt], Ah[m][0], Ah[m][1], Ah[m][2], Ah[m][3],
                             Bl[nt][0], Bl[nt][1]);
                }
        }
    }

    // ================= causal softmax on C fragments ========================
    // c0=(rA, 8nt+2t) c1=(rA,+1) c2=(rB,2t) c3=(rB,+1); rA=m16+g, rB=rA+8.
#pragma unroll
    for (int m = 0; m < 2; m++) {
        const int rA = m * 16 + (int)g;
        const int rB = rA + 8;
        float mxA = -1e30f, mxB = -1e30f;
#pragma unroll
        for (int nt = 0; nt < 4; nt++) {
            const int cc = 8 * nt + 2 * (int)t;
            if (cc     > rA) C[m][nt][0] = -1e30f;
            if (cc + 1 > rA) C[m][nt][1] = -1e30f;
            if (cc     > rB) C[m][nt][2] = -1e30f;
            if (cc + 1 > rB) C[m][nt][3] = -1e30f;
            mxA = fmaxf(mxA, fmaxf(C[m][nt][0], C[m][nt][1]));
            mxB = fmaxf(mxB, fmaxf(C[m][nt][2], C[m][nt][3]));
        }
        mxA = fmaxf(mxA, __shfl_xor_sync(0xffffffffu, mxA, 1));
        mxA = fmaxf(mxA, __shfl_xor_sync(0xffffffffu, mxA, 2));
        mxB = fmaxf(mxB, __shfl_xor_sync(0xffffffffu, mxB, 1));
        mxB = fmaxf(mxB, __shfl_xor_sync(0xffffffffu, mxB, 2));
        float sA = 0.f, sB = 0.f;
#pragma unroll
        for (int nt = 0; nt < 4; nt++) {
            C[m][nt][0] = __expf(C[m][nt][0] - mxA); sA += C[m][nt][0];
            C[m][nt][1] = __expf(C[m][nt][1] - mxA); sA += C[m][nt][1];
            C[m][nt][2] = __expf(C[m][nt][2] - mxB); sB += C[m][nt][2];
            C[m][nt][3] = __expf(C[m][nt][3] - mxB); sB += C[m][nt][3];
        }
        sA += __shfl_xor_sync(0xffffffffu, sA, 1);
        sA += __shfl_xor_sync(0xffffffffu, sA, 2);
        sB += __shfl_xor_sync(0xffffffffu, sB, 1);
        sB += __shfl_xor_sync(0xffffffffu, sB, 2);
        const float iA = 1.0f / sA;
        const float iB = 1.0f / sB;
#pragma unroll
        for (int nt = 0; nt < 4; nt++) {
            C[m][nt][0] *= iA;
            C[m][nt][1] *= iA;
            C[m][nt][2] *= iB;
            C[m][nt][3] *= iB;
        }
    }

    // ================= O = W V ; W A-frags == C frags (c0,c2,c1,c3) ========
    float* ob = out + bh * (2048u * 64u / 16u) * 16u;   // see note below
    // out offset = (b*2048 + jb*32)*1024 + h*64
    //            = (bh>>4)*2048*1024 + jb*32*1024 + (bh&15)*64
    ob = out + (bh >> 4) * (2048u * 1024u) + jb * (32u * 1024u) + (bh & 15u) * 64u;
#pragma unroll
    for (int half = 0; half < 2; half++) {
        float Cw[2][4][4];
#pragma unroll
        for (int m = 0; m < 2; m++)
#pragma unroll
            for (int nti = 0; nti < 4; nti++)
#pragma unroll
                for (int j = 0; j < 4; j++) Cw[m][nti][j] = 0.f;

#pragma unroll
        for (int kt = 0; kt < 4; kt++) {
            uint32_t Wh[2][4], Wl[2][4];
#pragma unroll
            for (int m = 0; m < 2; m++) {
                split_tf32(C[m][kt][0], Wh[m][0], Wl[m][0]);
                split_tf32(C[m][kt][2], Wh[m][1], Wl[m][1]);
                split_tf32(C[m][kt][1], Wh[m][2], Wl[m][2]);
                split_tf32(C[m][kt][3], Wh[m][3], Wl[m][3]);
            }
            const uint32_t p0 = kt * 8u + 2u * t;      // permuted key rows
            const float* vr0 = Vb + p0 * 64u;
            const float* vr1 = vr0 + 64u;
#pragma unroll
            for (int nti = 0; nti < 4; nti++) {
                const uint32_t ncol = (uint32_t)(half * 4 + nti) * 8u + g;
                float v0 = vr0[ncol];
                float v1 = vr1[ncol];
                uint32_t b0h, b0l, b1h, b1l;
                split_tf32(v0, b0h, b0l);
                split_tf32(v1, b1h, b1l);
#pragma unroll
                for (int m = 0; m < 2; m++) {
                    mma_tf32(Cw[m][nti], Wh[m][0], Wh[m][1], Wh[m][2], Wh[m][3],
                             b0h, b1h);
                    mma_tf32(Cw[m][nti], Wl[m][0], Wl[m][1], Wl[m][2], Wl[m][3],
                             b0h, b1h);
                    mma_tf32(Cw[m][nti], Wh[m][0], Wh[m][1], Wh[m][2], Wh[m][3],
                             b0l, b1l);
                }
            }
        }

        // stores: rows m16+g / +8, cols (half*4+nti)*8 + 2t (+1)
#pragma unroll
        for (int m = 0; m < 2; m++) {
            const uint32_t rA = (uint32_t)m * 16u + g;
#pragma unroll
            for (int nti = 0; nti < 4; nti++) {
                float* pA = ob + rA * 1024u + (uint32_t)(half * 4 + nti) * 8u + 2u * t;
                float* pB = pA + 8u * 1024u;
                *(float2*)pA = make_float2(Cw[m][nti][0], Cw[m][nti][1]);
                *(float2*)pB = make_float2(Cw[m][nti][2], Cw[m][nti][3]);
            }
        }
    }
}

extern "C" void kernel_launch(void* const* d_in, const int* in_sizes, int n_in,
                              void* d_out, int out_size) {
    const float* q = (const float*)d_in[0];
    const float* k = (const float*)d_in[1];
    const float* v = (const float*)d_in[2];
    float* out = (float*)d_out;

    rope_init_kernel<<<32, 32>>>();
    win_attn_kernel<<<8 * 16 * 64, 32>>>(q, k, v, out);
}